// round 14
// baseline (speedup 1.0000x reference)
#include <cuda_runtime.h>
#include <cuda_fp16.h>
#include <cstdint>

#define NA   100000
#define NB   800000
#define FEAT 64
#define HID  128
#define MAXD 32

typedef unsigned long long u64t;

// ---------------- scratch (device globals; no allocation allowed) ----------
__device__ __half g_A12h[(size_t)NA * 256]; // fp16: [atom][0:128]=a@Wb1[0:64], [128:256]=a@Wb1[64:128]
__device__ float g_agg[(size_t)NA * 64];    // mean of gathered updated bonds
__device__ float g_cb[HID];                 // bb1 + g@Wb1[192:256]
__device__ float g_ca[HID];                 // ba1 + g@Wa1[192:256]
__device__ float g_Wself[64 * HID];         // Wa1[0:64] + Wa1[128:192]
__device__ float g_bond_sum[FEAT];
__device__ float g_atom_sum[FEAT];

// ---------------- packed f32x2 helpers ------------------------------------
__device__ __forceinline__ void ffma2(u64t& d, u64t a, u64t b) {
    asm("fma.rn.f32x2 %0, %1, %2, %0;" : "+l"(d) : "l"(a), "l"(b));
}
__device__ __forceinline__ u64t pack2(float x, float y) {
    u64t r; asm("mov.b64 %0, {%1, %2};" : "=l"(r) : "f"(x), "f"(y)); return r;
}
__device__ __forceinline__ u64t pack1(float x) {
    u64t r; asm("mov.b64 %0, {%1, %1};" : "=l"(r) : "f"(x)); return r;
}
__device__ __forceinline__ float2 unpk(u64t v) {
    float2 f; asm("mov.b64 {%0, %1}, %2;" : "=f"(f.x), "=f"(f.y) : "l"(v)); return f;
}
// fast softplus: max(x,0) + log(1+exp(-|x|)); arg of log in (1,2] so __logf is safe
__device__ __forceinline__ float softplus_f(float x) {
    return fmaxf(x, 0.0f) + __logf(1.0f + __expf(-fabsf(x)));
}
__device__ __forceinline__ uint32_t h2pack(float x, float y) {
    __half2 h = __floats2half2_rn(x, y);
    return *(uint32_t*)&h;
}
__device__ __forceinline__ float2 h2unpack(uint32_t u) {
    return __half22float2(*(__half2*)&u);
}

// ---------------- K0: constants / zero accumulators ------------------------
__global__ void k0_prep(const float* __restrict__ g,
                        const float* __restrict__ Wb1, const float* __restrict__ bb1,
                        const float* __restrict__ Wa1, const float* __restrict__ ba1) {
    int t = threadIdx.x;  // 128 threads
    float cb = bb1[t], ca = ba1[t];
#pragma unroll 8
    for (int f = 0; f < 64; f++) {
        float gv = g[f];
        cb += gv * Wb1[(192 + f) * HID + t];
        ca += gv * Wa1[(192 + f) * HID + t];
    }
    g_cb[t] = cb;
    g_ca[t] = ca;
    if (t < FEAT) { g_bond_sum[t] = 0.0f; g_atom_sum[t] = 0.0f; }
    for (int i = t; i < 64 * HID; i += 128) {
        int k = i >> 7, j = i & 127;
        g_Wself[i] = Wa1[k * HID + j] + Wa1[(128 + k) * HID + j];
    }
}

// ---------------- K1: A12h = fp16(atom_features @ [Wb1[0:64]|Wb1[64:128]]) --
__global__ void __launch_bounds__(256, 2) k1_a12(const float* __restrict__ atom_features,
                                                 const float* __restrict__ Wb1) {
    extern __shared__ float sm[];
    float* sW = sm;            // 16384
    float* sA = sm + 16384;    // 4352

    int t = threadIdx.x;
    for (int i = t; i < 16384; i += 256) {
        int k = i >> 8, n = i & 255;
        sW[i] = (n < 128) ? Wb1[k * HID + n] : Wb1[(64 + k) * HID + (n - 128)];
    }
    int cg = t & 15, ag = t >> 4;
    const int NT = (NA + 63) / 64;
    __syncthreads();

    for (int tile = blockIdx.x; tile < NT; tile += gridDim.x) {
        int row0 = tile * 64;
#pragma unroll
        for (int r = 0; r < 4; r++) {
            int idx = t + r * 256;
            int a = idx >> 4, q = idx & 15;
            int row = row0 + a;
            float4 v = make_float4(0.f, 0.f, 0.f, 0.f);
            if (row < NA) v = *(const float4*)&atom_features[(size_t)row * FEAT + q * 4];
            *(float4*)&sA[a * 68 + q * 4] = v;
        }
        __syncthreads();

        u64t acc[4][8];
#pragma unroll
        for (int ai = 0; ai < 4; ai++)
#pragma unroll
            for (int p = 0; p < 8; p++) acc[ai][p] = 0ull;

        const float* wbase = sW + cg * 16;
        const float* abase = sA + (ag * 4) * 68;
#pragma unroll 4
        for (int k = 0; k < 64; k++) {
            const ulonglong2* wp = (const ulonglong2*)(wbase + (size_t)k * 256);
            ulonglong2 w0 = wp[0], w1 = wp[1], w2 = wp[2], w3 = wp[3];
#pragma unroll
            for (int ai = 0; ai < 4; ai++) {
                u64t bv = pack1(abase[ai * 68 + k]);
                ffma2(acc[ai][0], bv, w0.x); ffma2(acc[ai][1], bv, w0.y);
                ffma2(acc[ai][2], bv, w1.x); ffma2(acc[ai][3], bv, w1.y);
                ffma2(acc[ai][4], bv, w2.x); ffma2(acc[ai][5], bv, w2.y);
                ffma2(acc[ai][6], bv, w3.x); ffma2(acc[ai][7], bv, w3.y);
            }
        }
#pragma unroll
        for (int ai = 0; ai < 4; ai++) {
            int row = row0 + ag * 4 + ai;
            if (row >= NA) continue;
            uint32_t hp[8];
#pragma unroll
            for (int p = 0; p < 8; p++) {
                float2 f = unpk(acc[ai][p]);
                hp[p] = h2pack(f.x, f.y);
            }
            uint4* dst = (uint4*)&g_A12h[(size_t)row * 256 + cg * 16];
            dst[0] = make_uint4(hp[0], hp[1], hp[2], hp[3]);
            dst[1] = make_uint4(hp[4], hp[5], hp[6], hp[7]);
        }
        __syncthreads();
    }
}

// ---------------- K2: bond MLP, fp16 A12 gather PREFETCHED before staging ---
// 256 threads, 2 CTAs/SM, 128 bonds/tile. Indices read straight from gmem into
// registers, all 16 gathers issued, THEN bond staging + barrier cover latency.
__global__ void __launch_bounds__(256, 2) k2_bonds(
    const float* __restrict__ bond_features,
    const int* __restrict__ abi,
    const float* __restrict__ Wb1,
    const float* __restrict__ Wb2,
    const float* __restrict__ bb2,
    float* __restrict__ bonds_out)
{
    extern __shared__ float sm[];
    float* sWmid = sm;             // 8192 floats
    float* sBuf  = sm + 8192;      // 16896 floats: sBond(128x64) aliased under sH(128x132)
    float* sSum  = sm + 25088;     // 64
    int t = threadIdx.x;
    for (int i = t; i < 8192; i += 256) sWmid[i] = Wb1[128 * HID + i];
    if (t < 64) sSum[t] = 0.f;
    int hg = t & 15, bg = t >> 4;   // phase A: 8 hid cols, 8 bonds
    int fg = t & 7,  bg2 = t >> 3;  // phase B: 8 out cols, 4 bonds
    float cbv[8];
    float bb2v[8];
#pragma unroll
    for (int p = 0; p < 8; p++) { cbv[p] = g_cb[hg * 8 + p]; bb2v[p] = bb2[fg * 8 + p]; }
    float lsum[8] = {0.f,0.f,0.f,0.f,0.f,0.f,0.f,0.f};
    __syncthreads();

    for (int tile = blockIdx.x; tile < NB / 128; tile += gridDim.x) {
        int b0 = tile * 128;

        // ---- read this thread's 16 indices (L1-broadcast across hg group)
        const int4* ip = (const int4*)&abi[2 * (size_t)(b0 + bg * 8)];
        int4 i0 = ip[0], i1 = ip[1], i2 = ip[2], i3 = ip[3];

        // ---- issue all 16 fp16 gathers NOW (consumed after the barrier)
        uint4 u[8], v[8];
        u[0] = *(const uint4*)&g_A12h[(size_t)i0.x * 256 + hg * 8];
        v[0] = *(const uint4*)&g_A12h[(size_t)i0.y * 256 + 128 + hg * 8];
        u[1] = *(const uint4*)&g_A12h[(size_t)i0.z * 256 + hg * 8];
        v[1] = *(const uint4*)&g_A12h[(size_t)i0.w * 256 + 128 + hg * 8];
        u[2] = *(const uint4*)&g_A12h[(size_t)i1.x * 256 + hg * 8];
        v[2] = *(const uint4*)&g_A12h[(size_t)i1.y * 256 + 128 + hg * 8];
        u[3] = *(const uint4*)&g_A12h[(size_t)i1.z * 256 + hg * 8];
        v[3] = *(const uint4*)&g_A12h[(size_t)i1.w * 256 + 128 + hg * 8];
        u[4] = *(const uint4*)&g_A12h[(size_t)i2.x * 256 + hg * 8];
        v[4] = *(const uint4*)&g_A12h[(size_t)i2.y * 256 + 128 + hg * 8];
        u[5] = *(const uint4*)&g_A12h[(size_t)i2.z * 256 + hg * 8];
        v[5] = *(const uint4*)&g_A12h[(size_t)i2.w * 256 + 128 + hg * 8];
        u[6] = *(const uint4*)&g_A12h[(size_t)i3.x * 256 + hg * 8];
        v[6] = *(const uint4*)&g_A12h[(size_t)i3.y * 256 + 128 + hg * 8];
        u[7] = *(const uint4*)&g_A12h[(size_t)i3.z * 256 + hg * 8];
        v[7] = *(const uint4*)&g_A12h[(size_t)i3.w * 256 + 128 + hg * 8];

        // ---- stage 128x64 bond tile while gathers are in flight
#pragma unroll
        for (int r = 0; r < 8; r++) {
            int idx = t + r * 256;
            int b = idx >> 4, q = idx & 15;
            *(float4*)&sBuf[b * 64 + q * 4] =
                *(const float4*)&bond_features[(size_t)(b0 + b) * FEAT + q * 4];
        }
        __syncthreads();

        // ---- acc init from gathered fp16 rows + cb
        u64t acc[8][4];
#pragma unroll
        for (int bi = 0; bi < 8; bi++) {
            float2 x0 = h2unpack(u[bi].x), x1 = h2unpack(u[bi].y),
                   x2 = h2unpack(u[bi].z), x3 = h2unpack(u[bi].w);
            float2 y0 = h2unpack(v[bi].x), y1 = h2unpack(v[bi].y),
                   y2 = h2unpack(v[bi].z), y3 = h2unpack(v[bi].w);
            acc[bi][0] = pack2(x0.x + y0.x + cbv[0], x0.y + y0.y + cbv[1]);
            acc[bi][1] = pack2(x1.x + y1.x + cbv[2], x1.y + y1.y + cbv[3]);
            acc[bi][2] = pack2(x2.x + y2.x + cbv[4], x2.y + y2.y + cbv[5]);
            acc[bi][3] = pack2(x3.x + y3.x + cbv[6], x3.y + y3.y + cbv[7]);
        }

        // ---- phase A GEMM: += bond @ Wmid
        const float* wb = sWmid + hg * 8;
        const float* bp = sBuf + (bg * 8) * 64;
        for (int k4 = 0; k4 < 16; k4++) {
            float4 bv[8];
#pragma unroll
            for (int bi = 0; bi < 8; bi++)
                bv[bi] = *(const float4*)&bp[bi * 64 + k4 * 4];
#pragma unroll
            for (int kk = 0; kk < 4; kk++) {
                const ulonglong2* wp = (const ulonglong2*)(wb + (k4 * 4 + kk) * HID);
                ulonglong2 w01 = wp[0], w23 = wp[1];
#pragma unroll
                for (int bi = 0; bi < 8; bi++) {
                    float bs = (kk == 0) ? bv[bi].x : (kk == 1) ? bv[bi].y
                             : (kk == 2) ? bv[bi].z : bv[bi].w;
                    u64t bvv = pack1(bs);
                    ffma2(acc[bi][0], bvv, w01.x);
                    ffma2(acc[bi][1], bvv, w01.y);
                    ffma2(acc[bi][2], bvv, w23.x);
                    ffma2(acc[bi][3], bvv, w23.y);
                }
            }
        }
        __syncthreads();   // all sBond reads done; region becomes sH

        // softplus -> sH (stride 132)
#pragma unroll
        for (int bi = 0; bi < 8; bi++) {
            int b = bg * 8 + bi;
            float h[8];
#pragma unroll
            for (int p = 0; p < 4; p++) { float2 f = unpk(acc[bi][p]); h[2*p] = f.x; h[2*p+1] = f.y; }
#pragma unroll
            for (int p = 0; p < 8; p++) h[p] = softplus_f(h[p]);
            *(float4*)&sBuf[b * 132 + hg * 8]     = make_float4(h[0], h[1], h[2], h[3]);
            *(float4*)&sBuf[b * 132 + hg * 8 + 4] = make_float4(h[4], h[5], h[6], h[7]);
        }
        __syncthreads();

        // ---- phase B: out = h @ Wb2 + bb2 + bond (residual via L2-hot LDG)
        u64t acc2[4][4];
#pragma unroll
        for (int bi = 0; bi < 4; bi++) {
            int b = bg2 * 4 + bi;
            const float4* rp = (const float4*)&bond_features[(size_t)(b0 + b) * FEAT + fg * 8];
            float4 r0 = rp[0], r1 = rp[1];
            acc2[bi][0] = pack2(bb2v[0] + r0.x, bb2v[1] + r0.y);
            acc2[bi][1] = pack2(bb2v[2] + r0.z, bb2v[3] + r0.w);
            acc2[bi][2] = pack2(bb2v[4] + r1.x, bb2v[5] + r1.y);
            acc2[bi][3] = pack2(bb2v[6] + r1.z, bb2v[7] + r1.w);
        }
        const float* hbase = sBuf + (bg2 * 4) * 132;
        const float* w2 = Wb2 + fg * 8;
        for (int k4 = 0; k4 < 32; k4++) {
            float4 hv[4];
#pragma unroll
            for (int bi = 0; bi < 4; bi++)
                hv[bi] = *(const float4*)&hbase[bi * 132 + k4 * 4];
#pragma unroll
            for (int kk = 0; kk < 4; kk++) {
                const ulonglong2* wp = (const ulonglong2*)(w2 + (k4 * 4 + kk) * 64);
                ulonglong2 w01 = wp[0], w23 = wp[1];
#pragma unroll
                for (int bi = 0; bi < 4; bi++) {
                    float hs = (kk == 0) ? hv[bi].x : (kk == 1) ? hv[bi].y
                             : (kk == 2) ? hv[bi].z : hv[bi].w;
                    u64t hvv = pack1(hs);
                    ffma2(acc2[bi][0], hvv, w01.x);
                    ffma2(acc2[bi][1], hvv, w01.y);
                    ffma2(acc2[bi][2], hvv, w23.x);
                    ffma2(acc2[bi][3], hvv, w23.y);
                }
            }
        }
#pragma unroll
        for (int bi = 0; bi < 4; bi++) {
            int b = bg2 * 4 + bi;
            float o[8];
#pragma unroll
            for (int p = 0; p < 4; p++) { float2 f = unpk(acc2[bi][p]); o[2*p] = f.x; o[2*p+1] = f.y; }
#pragma unroll
            for (int p = 0; p < 8; p++) lsum[p] += o[p];
            float* dst = &bonds_out[(size_t)(b0 + b) * FEAT + fg * 8];
            *(float4*)dst       = make_float4(o[0], o[1], o[2], o[3]);
            *(float4*)(dst + 4) = make_float4(o[4], o[5], o[6], o[7]);
        }
        __syncthreads();
    }
#pragma unroll
    for (int p = 0; p < 8; p++) atomicAdd(&sSum[fg * 8 + p], lsum[p]);
    __syncthreads();
    if (t < 64) atomicAdd(&g_bond_sum[t], sSum[t]);
}

// ---------------- K3a: agg = mean of gathered updated bonds -----------------
__global__ void __launch_bounds__(256) k3a_agg(const int* __restrict__ bai,
                                               const float* __restrict__ bonds_out) {
    int t = threadIdx.x;
    int lane = t & 31, warp = t >> 5;
    int a = blockIdx.x * 8 + warp;
    int myidx = bai[(size_t)a * MAXD + lane];   // coalesced: lane d holds idx_d
    unsigned m = __ballot_sync(0xFFFFFFFFu, myidx >= 0);
    int cnt = __popc(m);
    float rs = 1.0f / (float)(cnt > 0 ? cnt : 1);
    float ax = 0.f, ay = 0.f;
#pragma unroll
    for (int d = 0; d < MAXD; d++) {
        int idx = __shfl_sync(0xFFFFFFFFu, myidx, d);
        if ((m >> d) & 1u) {
            float2 v = *(const float2*)&bonds_out[(size_t)idx * FEAT + lane * 2];
            ax += v.x; ay += v.y;
        }
    }
    float2 o; o.x = ax * rs; o.y = ay * rs;
    *(float2*)&g_agg[(size_t)a * FEAT + lane * 2] = o;
}

// ---------------- K3b: atom MLP (dense streaming) ---------------------------
__global__ void __launch_bounds__(256, 2) k3b_atoms(
    const float* __restrict__ atom_features,
    const float* __restrict__ Wa1,
    const float* __restrict__ Wa2,
    const float* __restrict__ ba2,
    float* __restrict__ atoms_out)
{
    extern __shared__ float sm[];
    float* sWcat = sm;            // 16384 floats (128x128)
    float* sBuf  = sm + 16384;    // 8448 floats: sX(64x132) aliased with sH(64x132)
    float* sSum  = sm + 24832;    // 64
    int t = threadIdx.x;
    for (int i = t; i < 16384; i += 256) {
        int k = i >> 7;
        sWcat[i] = (k < 64) ? g_Wself[i] : Wa1[i];
    }
    if (t < 64) sSum[t] = 0.f;
    int hg = t & 15, ag = t >> 4;
    int fg = t & 7,  ag2 = t >> 3;
    float cav[8], ba2v[8];
#pragma unroll
    for (int p = 0; p < 8; p++) { cav[p] = g_ca[hg * 8 + p]; ba2v[p] = ba2[fg * 8 + p]; }
    float lsum[8] = {0.f,0.f,0.f,0.f,0.f,0.f,0.f,0.f};
    __syncthreads();

    int ntiles = (NA + 63) / 64;
    for (int tile = blockIdx.x; tile < ntiles; tile += gridDim.x) {
        int a0 = tile * 64;
#pragma unroll
        for (int r = 0; r < 8; r++) {
            int idx = t + r * 256;
            int a = idx >> 5, q = idx & 31;
            float4 v = make_float4(0.f, 0.f, 0.f, 0.f);
            if (a0 + a < NA) {
                if (q < 16) v = *(const float4*)&atom_features[(size_t)(a0 + a) * FEAT + q * 4];
                else        v = *(const float4*)&g_agg[(size_t)(a0 + a) * FEAT + (q - 16) * 4];
            }
            *(float4*)&sBuf[a * 132 + q * 4] = v;
        }
        __syncthreads();

        u64t acc[4][4];
#pragma unroll
        for (int ai = 0; ai < 4; ai++)
#pragma unroll
            for (int p = 0; p < 4; p++)
                acc[ai][p] = pack2(cav[2 * p], cav[2 * p + 1]);
        const float* wb = sWcat + hg * 8;
        const float* xp = sBuf + (ag * 4) * 132;
        for (int k4 = 0; k4 < 32; k4++) {
            float4 xv[4];
#pragma unroll
            for (int ai = 0; ai < 4; ai++)
                xv[ai] = *(const float4*)&xp[ai * 132 + k4 * 4];
#pragma unroll
            for (int kk = 0; kk < 4; kk++) {
                const ulonglong2* wp = (const ulonglong2*)(wb + (k4 * 4 + kk) * HID);
                ulonglong2 w01 = wp[0], w23 = wp[1];
#pragma unroll
                for (int ai = 0; ai < 4; ai++) {
                    float xs = (kk == 0) ? xv[ai].x : (kk == 1) ? xv[ai].y
                             : (kk == 2) ? xv[ai].z : xv[ai].w;
                    u64t xvv = pack1(xs);
                    ffma2(acc[ai][0], xvv, w01.x);
                    ffma2(acc[ai][1], xvv, w01.y);
                    ffma2(acc[ai][2], xvv, w23.x);
                    ffma2(acc[ai][3], xvv, w23.y);
                }
            }
        }
        __syncthreads();

#pragma unroll
        for (int ai = 0; ai < 4; ai++) {
            int a = ag * 4 + ai;
            float h[8];
#pragma unroll
            for (int p = 0; p < 4; p++) { float2 f = unpk(acc[ai][p]); h[2*p] = f.x; h[2*p+1] = f.y; }
#pragma unroll
            for (int p = 0; p < 8; p++) h[p] = softplus_f(h[p]);
            *(float4*)&sBuf[a * 132 + hg * 8]     = make_float4(h[0], h[1], h[2], h[3]);
            *(float4*)&sBuf[a * 132 + hg * 8 + 4] = make_float4(h[4], h[5], h[6], h[7]);
        }
        __syncthreads();

        u64t acc2[2][4];
#pragma unroll
        for (int bi = 0; bi < 2; bi++) {
            int a = ag2 * 2 + bi;
            float4 r0 = make_float4(0.f,0.f,0.f,0.f), r1 = r0;
            if (a0 + a < NA) {
                const float4* rp = (const float4*)&atom_features[(size_t)(a0 + a) * FEAT + fg * 8];
                r0 = rp[0]; r1 = rp[1];
            }
            acc2[bi][0] = pack2(ba2v[0] + r0.x, ba2v[1] + r0.y);
            acc2[bi][1] = pack2(ba2v[2] + r0.z, ba2v[3] + r0.w);
            acc2[bi][2] = pack2(ba2v[4] + r1.x, ba2v[5] + r1.y);
            acc2[bi][3] = pack2(ba2v[6] + r1.z, ba2v[7] + r1.w);
        }
        const float* hb = sBuf + (ag2 * 2) * 132;
        const float* w2 = Wa2 + fg * 8;
        for (int k4 = 0; k4 < 32; k4++) {
            float4 hv[2];
#pragma unroll
            for (int bi = 0; bi < 2; bi++)
                hv[bi] = *(const float4*)&hb[bi * 132 + k4 * 4];
#pragma unroll
            for (int kk = 0; kk < 4; kk++) {
                const ulonglong2* wp = (const ulonglong2*)(w2 + (k4 * 4 + kk) * 64);
                ulonglong2 w01 = wp[0], w23 = wp[1];
#pragma unroll
                for (int bi = 0; bi < 2; bi++) {
                    float hs = (kk == 0) ? hv[bi].x : (kk == 1) ? hv[bi].y
                             : (kk == 2) ? hv[bi].z : hv[bi].w;
                    u64t hvv = pack1(hs);
                    ffma2(acc2[bi][0], hvv, w01.x);
                    ffma2(acc2[bi][1], hvv, w01.y);
                    ffma2(acc2[bi][2], hvv, w23.x);
                    ffma2(acc2[bi][3], hvv, w23.y);
                }
            }
        }
#pragma unroll
        for (int bi = 0; bi < 2; bi++) {
            int a = ag2 * 2 + bi;
            if (a0 + a >= NA) continue;
            float o[8];
#pragma unroll
            for (int p = 0; p < 4; p++) { float2 f = unpk(acc2[bi][p]); o[2*p] = f.x; o[2*p+1] = f.y; }
#pragma unroll
            for (int p = 0; p < 8; p++) lsum[p] += o[p];
            float* dst = &atoms_out[(size_t)(a0 + a) * FEAT + fg * 8];
            *(float4*)dst       = make_float4(o[0], o[1], o[2], o[3]);
            *(float4*)(dst + 4) = make_float4(o[4], o[5], o[6], o[7]);
        }
        __syncthreads();
    }
#pragma unroll
    for (int p = 0; p < 8; p++) atomicAdd(&sSum[fg * 8 + p], lsum[p]);
    __syncthreads();
    if (t < 64) atomicAdd(&g_atom_sum[t], sSum[t]);
}

// ---------------- K4: global update ----------------------------------------
__global__ void k4_global(const float* __restrict__ g,
                          const float* __restrict__ Wg1, const float* __restrict__ bg1,
                          const float* __restrict__ Wg2, const float* __restrict__ bg2,
                          float* __restrict__ out_global) {
    __shared__ float comb[192];
    __shared__ float sh[128];
    int t = threadIdx.x;  // 192 threads
    if (t < 64)       comb[t] = g_atom_sum[t] * (1.0f / (float)NA);
    else if (t < 128) comb[t] = g_bond_sum[t - 64] * (1.0f / (float)NB);
    else              comb[t] = g[t - 128];
    __syncthreads();
    if (t < 128) {
        float a = bg1[t];
#pragma unroll 8
        for (int k = 0; k < 192; k++) a += comb[k] * Wg1[k * HID + t];
        sh[t] = softplus_f(a);
    }
    __syncthreads();
    if (t < 64) {
        float a = bg2[t] + g[t];
#pragma unroll 8
        for (int k = 0; k < 128; k++) a += sh[k] * Wg2[k * 64 + t];
        out_global[t] = a;
    }
}

// ---------------- launch ----------------------------------------------------
extern "C" void kernel_launch(void* const* d_in, const int* in_sizes, int n_in,
                              void* d_out, int out_size) {
    const float* atom_features = (const float*)d_in[0];
    const float* bond_features = (const float*)d_in[1];
    const float* gfeat         = (const float*)d_in[2];
    const float* Wb1 = (const float*)d_in[3];
    const float* bb1 = (const float*)d_in[4];
    const float* Wb2 = (const float*)d_in[5];
    const float* bb2 = (const float*)d_in[6];
    const float* Wa1 = (const float*)d_in[7];
    const float* ba1 = (const float*)d_in[8];
    const float* Wa2 = (const float*)d_in[9];
    const float* ba2 = (const float*)d_in[10];
    const float* Wg1 = (const float*)d_in[11];
    const float* bg1 = (const float*)d_in[12];
    const float* Wg2 = (const float*)d_in[13];
    const float* bg2 = (const float*)d_in[14];
    const int* abi = (const int*)d_in[15];
    const int* bai = (const int*)d_in[16];

    float* out        = (float*)d_out;
    float* atoms_out  = out;
    float* bonds_out  = out + (size_t)NA * FEAT;
    float* global_out = out + (size_t)NA * FEAT + (size_t)NB * FEAT;

    const int smem1  = 20736 * 4;   // 82,944 B  (2 CTAs/SM)
    const int smem2  = 25152 * 4;   // 100,608 B (2 CTAs/SM)
    const int smem3b = 24896 * 4;   // 99,584 B  (2 CTAs/SM)
    cudaFuncSetAttribute(k1_a12,    cudaFuncAttributeMaxDynamicSharedMemorySize, smem1);
    cudaFuncSetAttribute(k2_bonds,  cudaFuncAttributeMaxDynamicSharedMemorySize, smem2);
    cudaFuncSetAttribute(k3b_atoms, cudaFuncAttributeMaxDynamicSharedMemorySize, smem3b);

    k0_prep<<<1, 128>>>(gfeat, Wb1, bb1, Wa1, ba1);
    k1_a12<<<296, 256, smem1>>>(atom_features, Wb1);
    k2_bonds<<<296, 256, smem2>>>(bond_features, abi, Wb1, Wb2, bb2, bonds_out);
    k3a_agg<<<NA / 8, 256>>>(bai, bonds_out);
    k3b_atoms<<<296, 256, smem3b>>>(atom_features, Wa1, Wa2, ba2, atoms_out);
    k4_global<<<1, 192>>>(gfeat, Wg1, bg1, Wg2, bg2, global_out);
}

// round 15
// speedup vs baseline: 1.5822x; 1.5822x over previous
#include <cuda_runtime.h>
#include <cuda_fp16.h>
#include <cstdint>

#define NA   100000
#define NB   800000
#define FEAT 64
#define HID  128
#define MAXD 32

typedef unsigned long long u64t;

// ---------------- scratch (device globals; no allocation allowed) ----------
__device__ __half g_A12h[(size_t)NA * 256]; // fp16: [atom][0:128]=a@Wb1[0:64], [128:256]=a@Wb1[64:128]
__device__ float g_agg[(size_t)NA * 64];    // mean of gathered updated bonds
__device__ float g_cb[HID];                 // bb1 + g@Wb1[192:256]
__device__ float g_ca[HID];                 // ba1 + g@Wa1[192:256]
__device__ float g_Wself[64 * HID];         // Wa1[0:64] + Wa1[128:192]
__device__ float g_bond_sum[FEAT];
__device__ float g_atom_sum[FEAT];

// ---------------- packed f32x2 helpers ------------------------------------
__device__ __forceinline__ void ffma2(u64t& d, u64t a, u64t b) {
    asm("fma.rn.f32x2 %0, %1, %2, %0;" : "+l"(d) : "l"(a), "l"(b));
}
__device__ __forceinline__ u64t pack2(float x, float y) {
    u64t r; asm("mov.b64 %0, {%1, %2};" : "=l"(r) : "f"(x), "f"(y)); return r;
}
__device__ __forceinline__ u64t pack1(float x) {
    u64t r; asm("mov.b64 %0, {%1, %1};" : "=l"(r) : "f"(x)); return r;
}
__device__ __forceinline__ float2 unpk(u64t v) {
    float2 f; asm("mov.b64 {%0, %1}, %2;" : "=f"(f.x), "=f"(f.y) : "l"(v)); return f;
}
// fast softplus: max(x,0) + log(1+exp(-|x|)); arg of log in (1,2] so __logf is safe
__device__ __forceinline__ float softplus_f(float x) {
    return fmaxf(x, 0.0f) + __logf(1.0f + __expf(-fabsf(x)));
}
__device__ __forceinline__ uint32_t h2pack(float x, float y) {
    __half2 h = __floats2half2_rn(x, y);
    return *(uint32_t*)&h;
}
__device__ __forceinline__ float2 h2unpack(uint32_t u) {
    return __half22float2(*(__half2*)&u);
}

// ---------------- K0: constants / zero accumulators ------------------------
__global__ void k0_prep(const float* __restrict__ g,
                        const float* __restrict__ Wb1, const float* __restrict__ bb1,
                        const float* __restrict__ Wa1, const float* __restrict__ ba1) {
    int t = threadIdx.x;  // 128 threads
    float cb = bb1[t], ca = ba1[t];
#pragma unroll 8
    for (int f = 0; f < 64; f++) {
        float gv = g[f];
        cb += gv * Wb1[(192 + f) * HID + t];
        ca += gv * Wa1[(192 + f) * HID + t];
    }
    g_cb[t] = cb;
    g_ca[t] = ca;
    if (t < FEAT) { g_bond_sum[t] = 0.0f; g_atom_sum[t] = 0.0f; }
    for (int i = t; i < 64 * HID; i += 128) {
        int k = i >> 7, j = i & 127;
        g_Wself[i] = Wa1[k * HID + j] + Wa1[(128 + k) * HID + j];
    }
}

// ---------------- K1: A12h = fp16(atom_features @ [Wb1[0:64]|Wb1[64:128]]) --
// PERSISTENT: weights staged once per block, then loop over 64-atom tiles.
__global__ void __launch_bounds__(256, 2) k1_a12(const float* __restrict__ atom_features,
                                                 const float* __restrict__ Wb1) {
    extern __shared__ float sm[];
    float* sW = sm;            // 16384
    float* sA = sm + 16384;    // 4352

    int t = threadIdx.x;
    for (int i = t; i < 16384; i += 256) {
        int k = i >> 8, n = i & 255;
        sW[i] = (n < 128) ? Wb1[k * HID + n] : Wb1[(64 + k) * HID + (n - 128)];
    }
    int cg = t & 15, ag = t >> 4;
    const int NT = (NA + 63) / 64;
    __syncthreads();

    for (int tile = blockIdx.x; tile < NT; tile += gridDim.x) {
        int row0 = tile * 64;
#pragma unroll
        for (int r = 0; r < 4; r++) {
            int idx = t + r * 256;
            int a = idx >> 4, q = idx & 15;
            int row = row0 + a;
            float4 v = make_float4(0.f, 0.f, 0.f, 0.f);
            if (row < NA) v = __ldcs((const float4*)&atom_features[(size_t)row * FEAT + q * 4]);
            *(float4*)&sA[a * 68 + q * 4] = v;
        }
        __syncthreads();

        u64t acc[4][8];
#pragma unroll
        for (int ai = 0; ai < 4; ai++)
#pragma unroll
            for (int p = 0; p < 8; p++) acc[ai][p] = 0ull;

        const float* wbase = sW + cg * 16;
        const float* abase = sA + (ag * 4) * 68;
#pragma unroll 4
        for (int k = 0; k < 64; k++) {
            const ulonglong2* wp = (const ulonglong2*)(wbase + (size_t)k * 256);
            ulonglong2 w0 = wp[0], w1 = wp[1], w2 = wp[2], w3 = wp[3];
#pragma unroll
            for (int ai = 0; ai < 4; ai++) {
                u64t bv = pack1(abase[ai * 68 + k]);
                ffma2(acc[ai][0], bv, w0.x); ffma2(acc[ai][1], bv, w0.y);
                ffma2(acc[ai][2], bv, w1.x); ffma2(acc[ai][3], bv, w1.y);
                ffma2(acc[ai][4], bv, w2.x); ffma2(acc[ai][5], bv, w2.y);
                ffma2(acc[ai][6], bv, w3.x); ffma2(acc[ai][7], bv, w3.y);
            }
        }
#pragma unroll
        for (int ai = 0; ai < 4; ai++) {
            int row = row0 + ag * 4 + ai;
            if (row >= NA) continue;
            uint32_t hp[8];
#pragma unroll
            for (int p = 0; p < 8; p++) {
                float2 f = unpk(acc[ai][p]);
                hp[p] = h2pack(f.x, f.y);
            }
            uint4* dst = (uint4*)&g_A12h[(size_t)row * 256 + cg * 16];
            dst[0] = make_uint4(hp[0], hp[1], hp[2], hp[3]);
            dst[1] = make_uint4(hp[4], hp[5], hp[6], hp[7]);
        }
        __syncthreads();
    }
}

// ---------------- K2: bond MLP with fused fp16-A12 gather (R13 champion) ----
// 256 threads, 2 CTAs/SM, 128 bonds/tile. Gathers issued at acc-init, right
// after the barrier; streaming hints on single-use data to protect A12 in L2.
__global__ void __launch_bounds__(256, 2) k2_bonds(
    const float* __restrict__ bond_features,
    const int* __restrict__ abi,
    const float* __restrict__ Wb1,
    const float* __restrict__ Wb2,
    const float* __restrict__ bb2,
    float* __restrict__ bonds_out)
{
    extern __shared__ float sm[];
    float* sWmid = sm;             // 8192 floats
    float* sBuf  = sm + 8192;      // 16896 floats: sBond(128x64) aliased under sH(128x132)
    float* sSum  = sm + 25088;     // 64
    int*   sIdx  = (int*)(sm + 25152); // 256 ints
    int t = threadIdx.x;
    for (int i = t; i < 8192; i += 256) sWmid[i] = Wb1[128 * HID + i];
    if (t < 64) sSum[t] = 0.f;
    int hg = t & 15, bg = t >> 4;   // phase A: 8 hid cols, 8 bonds
    int fg = t & 7,  bg2 = t >> 3;  // phase B: 8 out cols, 4 bonds
    float cbv[8];
    float bb2v[8];
#pragma unroll
    for (int p = 0; p < 8; p++) { cbv[p] = g_cb[hg * 8 + p]; bb2v[p] = bb2[fg * 8 + p]; }
    float lsum[8] = {0.f,0.f,0.f,0.f,0.f,0.f,0.f,0.f};
    __syncthreads();

    for (int tile = blockIdx.x; tile < NB / 128; tile += gridDim.x) {
        int b0 = tile * 128;
        // stage idx + 128x64 bond tile (stride 64); first read keeps L2 copy
        if (t < 256) sIdx[t] = __ldcs(&abi[(size_t)b0 * 2 + t]);
#pragma unroll
        for (int r = 0; r < 8; r++) {
            int idx = t + r * 256;
            int b = idx >> 4, q = idx & 15;
            *(float4*)&sBuf[b * 64 + q * 4] =
                *(const float4*)&bond_features[(size_t)(b0 + b) * FEAT + q * 4];
        }
        __syncthreads();

        // ---- phase A init: gathered fp16 A12 rows (16 independent 16B LDGs)
        int ia[8], ja[8];
#pragma unroll
        for (int bi = 0; bi < 8; bi++) {
            int b = bg * 8 + bi;
            ia[bi] = sIdx[2 * b];
            ja[bi] = sIdx[2 * b + 1];
        }
        u64t acc[8][4];
#pragma unroll
        for (int bi = 0; bi < 8; bi++) {
            uint4 u = *(const uint4*)&g_A12h[(size_t)ia[bi] * 256 + hg * 8];
            uint4 v = *(const uint4*)&g_A12h[(size_t)ja[bi] * 256 + 128 + hg * 8];
            float2 x0 = h2unpack(u.x), x1 = h2unpack(u.y),
                   x2 = h2unpack(u.z), x3 = h2unpack(u.w);
            float2 y0 = h2unpack(v.x), y1 = h2unpack(v.y),
                   y2 = h2unpack(v.z), y3 = h2unpack(v.w);
            acc[bi][0] = pack2(x0.x + y0.x + cbv[0], x0.y + y0.y + cbv[1]);
            acc[bi][1] = pack2(x1.x + y1.x + cbv[2], x1.y + y1.y + cbv[3]);
            acc[bi][2] = pack2(x2.x + y2.x + cbv[4], x2.y + y2.y + cbv[5]);
            acc[bi][3] = pack2(x3.x + y3.x + cbv[6], x3.y + y3.y + cbv[7]);
        }

        // ---- phase A GEMM: += bond @ Wmid
        const float* wb = sWmid + hg * 8;
        const float* bp = sBuf + (bg * 8) * 64;
        for (int k4 = 0; k4 < 16; k4++) {
            float4 bv[8];
#pragma unroll
            for (int bi = 0; bi < 8; bi++)
                bv[bi] = *(const float4*)&bp[bi * 64 + k4 * 4];
#pragma unroll
            for (int kk = 0; kk < 4; kk++) {
                const ulonglong2* wp = (const ulonglong2*)(wb + (k4 * 4 + kk) * HID);
                ulonglong2 w01 = wp[0], w23 = wp[1];
#pragma unroll
                for (int bi = 0; bi < 8; bi++) {
                    float bs = (kk == 0) ? bv[bi].x : (kk == 1) ? bv[bi].y
                             : (kk == 2) ? bv[bi].z : bv[bi].w;
                    u64t bvv = pack1(bs);
                    ffma2(acc[bi][0], bvv, w01.x);
                    ffma2(acc[bi][1], bvv, w01.y);
                    ffma2(acc[bi][2], bvv, w23.x);
                    ffma2(acc[bi][3], bvv, w23.y);
                }
            }
        }
        __syncthreads();   // all sBond reads done; region becomes sH

        // softplus -> sH (stride 132)
#pragma unroll
        for (int bi = 0; bi < 8; bi++) {
            int b = bg * 8 + bi;
            float h[8];
#pragma unroll
            for (int p = 0; p < 4; p++) { float2 f = unpk(acc[bi][p]); h[2*p] = f.x; h[2*p+1] = f.y; }
#pragma unroll
            for (int p = 0; p < 8; p++) h[p] = softplus_f(h[p]);
            *(float4*)&sBuf[b * 132 + hg * 8]     = make_float4(h[0], h[1], h[2], h[3]);
            *(float4*)&sBuf[b * 132 + hg * 8 + 4] = make_float4(h[4], h[5], h[6], h[7]);
        }
        __syncthreads();

        // ---- phase B: out = h @ Wb2 + bb2 + bond (residual: LAST use -> evict-first)
        u64t acc2[4][4];
#pragma unroll
        for (int bi = 0; bi < 4; bi++) {
            int b = bg2 * 4 + bi;
            const float4* rp = (const float4*)&bond_features[(size_t)(b0 + b) * FEAT + fg * 8];
            float4 r0 = __ldcs(rp), r1 = __ldcs(rp + 1);
            acc2[bi][0] = pack2(bb2v[0] + r0.x, bb2v[1] + r0.y);
            acc2[bi][1] = pack2(bb2v[2] + r0.z, bb2v[3] + r0.w);
            acc2[bi][2] = pack2(bb2v[4] + r1.x, bb2v[5] + r1.y);
            acc2[bi][3] = pack2(bb2v[6] + r1.z, bb2v[7] + r1.w);
        }
        const float* hbase = sBuf + (bg2 * 4) * 132;
        const float* w2 = Wb2 + fg * 8;
        for (int k4 = 0; k4 < 32; k4++) {
            float4 hv[4];
#pragma unroll
            for (int bi = 0; bi < 4; bi++)
                hv[bi] = *(const float4*)&hbase[bi * 132 + k4 * 4];
#pragma unroll
            for (int kk = 0; kk < 4; kk++) {
                const ulonglong2* wp = (const ulonglong2*)(w2 + (k4 * 4 + kk) * 64);
                ulonglong2 w01 = wp[0], w23 = wp[1];
#pragma unroll
                for (int bi = 0; bi < 4; bi++) {
                    float hs = (kk == 0) ? hv[bi].x : (kk == 1) ? hv[bi].y
                             : (kk == 2) ? hv[bi].z : hv[bi].w;
                    u64t hvv = pack1(hs);
                    ffma2(acc2[bi][0], hvv, w01.x);
                    ffma2(acc2[bi][1], hvv, w01.y);
                    ffma2(acc2[bi][2], hvv, w23.x);
                    ffma2(acc2[bi][3], hvv, w23.y);
                }
            }
        }
#pragma unroll
        for (int bi = 0; bi < 4; bi++) {
            int b = bg2 * 4 + bi;
            float o[8];
#pragma unroll
            for (int p = 0; p < 4; p++) { float2 f = unpk(acc2[bi][p]); o[2*p] = f.x; o[2*p+1] = f.y; }
#pragma unroll
            for (int p = 0; p < 8; p++) lsum[p] += o[p];
            float* dst = &bonds_out[(size_t)(b0 + b) * FEAT + fg * 8];
            *(float4*)dst       = make_float4(o[0], o[1], o[2], o[3]);
            *(float4*)(dst + 4) = make_float4(o[4], o[5], o[6], o[7]);
        }
        __syncthreads();
    }
#pragma unroll
    for (int p = 0; p < 8; p++) atomicAdd(&sSum[fg * 8 + p], lsum[p]);
    __syncthreads();
    if (t < 64) atomicAdd(&g_bond_sum[t], sSum[t]);
}

// ---------------- K3a: agg = mean of gathered updated bonds -----------------
__global__ void __launch_bounds__(256) k3a_agg(const int* __restrict__ bai,
                                               const float* __restrict__ bonds_out) {
    int t = threadIdx.x;
    int lane = t & 31, warp = t >> 5;
    int a = blockIdx.x * 8 + warp;
    int myidx = __ldcs(&bai[(size_t)a * MAXD + lane]);   // coalesced: lane d holds idx_d
    unsigned m = __ballot_sync(0xFFFFFFFFu, myidx >= 0);
    int cnt = __popc(m);
    float rs = 1.0f / (float)(cnt > 0 ? cnt : 1);
    float ax = 0.f, ay = 0.f;
#pragma unroll
    for (int d = 0; d < MAXD; d++) {
        int idx = __shfl_sync(0xFFFFFFFFu, myidx, d);
        if ((m >> d) & 1u) {
            float2 v = *(const float2*)&bonds_out[(size_t)idx * FEAT + lane * 2];
            ax += v.x; ay += v.y;
        }
    }
    float2 o; o.x = ax * rs; o.y = ay * rs;
    *(float2*)&g_agg[(size_t)a * FEAT + lane * 2] = o;
}

// ---------------- K3b: atom MLP (dense streaming) ---------------------------
__global__ void __launch_bounds__(256, 2) k3b_atoms(
    const float* __restrict__ atom_features,
    const float* __restrict__ Wa1,
    const float* __restrict__ Wa2,
    const float* __restrict__ ba2,
    float* __restrict__ atoms_out)
{
    extern __shared__ float sm[];
    float* sWcat = sm;            // 16384 floats (128x128)
    float* sBuf  = sm + 16384;    // 8448 floats: sX(64x132) aliased with sH(64x132)
    float* sSum  = sm + 24832;    // 64
    int t = threadIdx.x;
    for (int i = t; i < 16384; i += 256) {
        int k = i >> 7;
        sWcat[i] = (k < 64) ? g_Wself[i] : Wa1[i];
    }
    if (t < 64) sSum[t] = 0.f;
    int hg = t & 15, ag = t >> 4;
    int fg = t & 7,  ag2 = t >> 3;
    float cav[8], ba2v[8];
#pragma unroll
    for (int p = 0; p < 8; p++) { cav[p] = g_ca[hg * 8 + p]; ba2v[p] = ba2[fg * 8 + p]; }
    float lsum[8] = {0.f,0.f,0.f,0.f,0.f,0.f,0.f,0.f};
    __syncthreads();

    int ntiles = (NA + 63) / 64;
    for (int tile = blockIdx.x; tile < ntiles; tile += gridDim.x) {
        int a0 = tile * 64;
#pragma unroll
        for (int r = 0; r < 8; r++) {
            int idx = t + r * 256;
            int a = idx >> 5, q = idx & 31;
            float4 v = make_float4(0.f, 0.f, 0.f, 0.f);
            if (a0 + a < NA) {
                if (q < 16) v = *(const float4*)&atom_features[(size_t)(a0 + a) * FEAT + q * 4];
                else        v = __ldcs((const float4*)&g_agg[(size_t)(a0 + a) * FEAT + (q - 16) * 4]);
            }
            *(float4*)&sBuf[a * 132 + q * 4] = v;
        }
        __syncthreads();

        u64t acc[4][4];
#pragma unroll
        for (int ai = 0; ai < 4; ai++)
#pragma unroll
            for (int p = 0; p < 4; p++)
                acc[ai][p] = pack2(cav[2 * p], cav[2 * p + 1]);
        const float* wb = sWcat + hg * 8;
        const float* xp = sBuf + (ag * 4) * 132;
        for (int k4 = 0; k4 < 32; k4++) {
            float4 xv[4];
#pragma unroll
            for (int ai = 0; ai < 4; ai++)
                xv[ai] = *(const float4*)&xp[ai * 132 + k4 * 4];
#pragma unroll
            for (int kk = 0; kk < 4; kk++) {
                const ulonglong2* wp = (const ulonglong2*)(wb + (k4 * 4 + kk) * HID);
                ulonglong2 w01 = wp[0], w23 = wp[1];
#pragma unroll
                for (int ai = 0; ai < 4; ai++) {
                    float xs = (kk == 0) ? xv[ai].x : (kk == 1) ? xv[ai].y
                             : (kk == 2) ? xv[ai].z : xv[ai].w;
                    u64t xvv = pack1(xs);
                    ffma2(acc[ai][0], xvv, w01.x);
                    ffma2(acc[ai][1], xvv, w01.y);
                    ffma2(acc[ai][2], xvv, w23.x);
                    ffma2(acc[ai][3], xvv, w23.y);
                }
            }
        }
        __syncthreads();

#pragma unroll
        for (int ai = 0; ai < 4; ai++) {
            int a = ag * 4 + ai;
            float h[8];
#pragma unroll
            for (int p = 0; p < 4; p++) { float2 f = unpk(acc[ai][p]); h[2*p] = f.x; h[2*p+1] = f.y; }
#pragma unroll
            for (int p = 0; p < 8; p++) h[p] = softplus_f(h[p]);
            *(float4*)&sBuf[a * 132 + hg * 8]     = make_float4(h[0], h[1], h[2], h[3]);
            *(float4*)&sBuf[a * 132 + hg * 8 + 4] = make_float4(h[4], h[5], h[6], h[7]);
        }
        __syncthreads();

        u64t acc2[2][4];
#pragma unroll
        for (int bi = 0; bi < 2; bi++) {
            int a = ag2 * 2 + bi;
            float4 r0 = make_float4(0.f,0.f,0.f,0.f), r1 = r0;
            if (a0 + a < NA) {
                const float4* rp = (const float4*)&atom_features[(size_t)(a0 + a) * FEAT + fg * 8];
                r0 = __ldcs(rp); r1 = __ldcs(rp + 1);
            }
            acc2[bi][0] = pack2(ba2v[0] + r0.x, ba2v[1] + r0.y);
            acc2[bi][1] = pack2(ba2v[2] + r0.z, ba2v[3] + r0.w);
            acc2[bi][2] = pack2(ba2v[4] + r1.x, ba2v[5] + r1.y);
            acc2[bi][3] = pack2(ba2v[6] + r1.z, ba2v[7] + r1.w);
        }
        const float* hb = sBuf + (ag2 * 2) * 132;
        const float* w2 = Wa2 + fg * 8;
        for (int k4 = 0; k4 < 32; k4++) {
            float4 hv[2];
#pragma unroll
            for (int bi = 0; bi < 2; bi++)
                hv[bi] = *(const float4*)&hb[bi * 132 + k4 * 4];
#pragma unroll
            for (int kk = 0; kk < 4; kk++) {
                const ulonglong2* wp = (const ulonglong2*)(w2 + (k4 * 4 + kk) * 64);
                ulonglong2 w01 = wp[0], w23 = wp[1];
#pragma unroll
                for (int bi = 0; bi < 2; bi++) {
                    float hs = (kk == 0) ? hv[bi].x : (kk == 1) ? hv[bi].y
                             : (kk == 2) ? hv[bi].z : hv[bi].w;
                    u64t hvv = pack1(hs);
                    ffma2(acc2[bi][0], hvv, w01.x);
                    ffma2(acc2[bi][1], hvv, w01.y);
                    ffma2(acc2[bi][2], hvv, w23.x);
                    ffma2(acc2[bi][3], hvv, w23.y);
                }
            }
        }
#pragma unroll
        for (int bi = 0; bi < 2; bi++) {
            int a = ag2 * 2 + bi;
            if (a0 + a >= NA) continue;
            float o[8];
#pragma unroll
            for (int p = 0; p < 4; p++) { float2 f = unpk(acc2[bi][p]); o[2*p] = f.x; o[2*p+1] = f.y; }
#pragma unroll
            for (int p = 0; p < 8; p++) lsum[p] += o[p];
            float* dst = &atoms_out[(size_t)(a0 + a) * FEAT + fg * 8];
            *(float4*)dst       = make_float4(o[0], o[1], o[2], o[3]);
            *(float4*)(dst + 4) = make_float4(o[4], o[5], o[6], o[7]);
        }
        __syncthreads();
    }
#pragma unroll
    for (int p = 0; p < 8; p++) atomicAdd(&sSum[fg * 8 + p], lsum[p]);
    __syncthreads();
    if (t < 64) atomicAdd(&g_atom_sum[t], sSum[t]);
}

// ---------------- K4: global update ----------------------------------------
__global__ void k4_global(const float* __restrict__ g,
                          const float* __restrict__ Wg1, const float* __restrict__ bg1,
                          const float* __restrict__ Wg2, const float* __restrict__ bg2,
                          float* __restrict__ out_global) {
    __shared__ float comb[192];
    __shared__ float sh[128];
    int t = threadIdx.x;  // 192 threads
    if (t < 64)       comb[t] = g_atom_sum[t] * (1.0f / (float)NA);
    else if (t < 128) comb[t] = g_bond_sum[t - 64] * (1.0f / (float)NB);
    else              comb[t] = g[t - 128];
    __syncthreads();
    if (t < 128) {
        float a = bg1[t];
#pragma unroll 8
        for (int k = 0; k < 192; k++) a += comb[k] * Wg1[k * HID + t];
        sh[t] = softplus_f(a);
    }
    __syncthreads();
    if (t < 64) {
        float a = bg2[t] + g[t];
#pragma unroll 8
        for (int k = 0; k < 128; k++) a += sh[k] * Wg2[k * 64 + t];
        out_global[t] = a;
    }
}

// ---------------- launch ----------------------------------------------------
extern "C" void kernel_launch(void* const* d_in, const int* in_sizes, int n_in,
                              void* d_out, int out_size) {
    const float* atom_features = (const float*)d_in[0];
    const float* bond_features = (const float*)d_in[1];
    const float* gfeat         = (const float*)d_in[2];
    const float* Wb1 = (const float*)d_in[3];
    const float* bb1 = (const float*)d_in[4];
    const float* Wb2 = (const float*)d_in[5];
    const float* bb2 = (const float*)d_in[6];
    const float* Wa1 = (const float*)d_in[7];
    const float* ba1 = (const float*)d_in[8];
    const float* Wa2 = (const float*)d_in[9];
    const float* ba2 = (const float*)d_in[10];
    const float* Wg1 = (const float*)d_in[11];
    const float* bg1 = (const float*)d_in[12];
    const float* Wg2 = (const float*)d_in[13];
    const float* bg2 = (const float*)d_in[14];
    const int* abi = (const int*)d_in[15];
    const int* bai = (const int*)d_in[16];

    float* out        = (float*)d_out;
    float* atoms_out  = out;
    float* bonds_out  = out + (size_t)NA * FEAT;
    float* global_out = out + (size_t)NA * FEAT + (size_t)NB * FEAT;

    const int smem1  = 20736 * 4;   // 82,944 B  (2 CTAs/SM)
    const int smem2  = 25408 * 4;   // 101,632 B (2 CTAs/SM)
    const int smem3b = 24896 * 4;   // 99,584 B  (2 CTAs/SM)
    cudaFuncSetAttribute(k1_a12,    cudaFuncAttributeMaxDynamicSharedMemorySize, smem1);
    cudaFuncSetAttribute(k2_bonds,  cudaFuncAttributeMaxDynamicSharedMemorySize, smem2);
    cudaFuncSetAttribute(k3b_atoms, cudaFuncAttributeMaxDynamicSharedMemorySize, smem3b);

    k0_prep<<<1, 128>>>(gfeat, Wb1, bb1, Wa1, ba1);
    k1_a12<<<296, 256, smem1>>>(atom_features, Wb1);
    k2_bonds<<<296, 256, smem2>>>(bond_features, abi, Wb1, Wb2, bb2, bonds_out);
    k3a_agg<<<NA / 8, 256>>>(bai, bonds_out);
    k3b_atoms<<<296, 256, smem3b>>>(atom_features, Wa1, Wa2, ba2, atoms_out);
    k4_global<<<1, 192>>>(gfeat, Wg1, bg1, Wg2, bg2, global_out);
}